// round 12
// baseline (speedup 1.0000x reference)
#include <cuda_runtime.h>
#include <cuda_fp16.h>
#include <cstdint>

// ---------------- problem constants ----------------
#define OUT_C_OFF   (2 * 32 * 512)
#define OUT_ENC_OFF (4 * 32 * 512)

// ---------------- device scratch (no allocs allowed) ----------------
// GEMM operands rn-rounded to fp16, k-permuted within each 16-group to
// [0,1,8,9, 2,3,10,11, 4,5,12,13, 6,7,14,15] so each thread's m16n8k16
// fragment (k = 2q,2q+1,2q+8,2q+9) is one contiguous LDS.64.
__device__ __half g_a0[(size_t)8192 * 512];     // gathered embeddings
__device__ __half g_w0[(size_t)3072 * 512];     // L0 weights, gate-major: i_f,g_f,o_f,i_b,g_b,o_b
__device__ __half g_w1[(size_t)3072 * 1024];    // L1 weights, gate-major
__device__ __half g_inp1[(size_t)8192 * 1024];  // L0 output h (permuted): [h_f | h_b]

// ---------------- helpers ----------------
__device__ __forceinline__ float tanh_ap(float x) {
    float r; asm("tanh.approx.f32 %0, %1;" : "=f"(r) : "f"(x)); return r;
}
__device__ __forceinline__ float sigm(float x) { return 0.5f * tanh_ap(0.5f * x) + 0.5f; }

__device__ __forceinline__ uint32_t s2u(const void* p) {
    uint32_t a;
    asm("{ .reg .u64 t; cvta.to.shared.u64 t, %1; cvt.u32.u64 %0, t; }" : "=r"(a) : "l"(p));
    return a;
}
__device__ __forceinline__ void cp16(uint32_t d, const void* s) {
    asm volatile("cp.async.cg.shared.global [%0], [%1], 16;" :: "r"(d), "l"(s));
}

// logical k L -> stored slot (within 16-group)
__device__ __forceinline__ int kslot16(int L) {
    const int r = L & 15, base = L & ~15;
    return base + ((r < 8) ? (((r >> 1) << 2) + (r & 1))
                           : ((((r - 8) >> 1) << 2) + 2 + (r & 1)));
}

// gate g (0..5 = i_f,g_f,o_f,i_b,g_b,o_b) -> row base in (2,4H) space
__device__ __forceinline__ int gbase(int g) {
    const int d = (g >= 3) ? 1 : 0;
    const int g3 = g - 3 * d;
    return d * 2048 + ((g3 == 1) ? 1024 : (g3 == 2) ? 1536 : 0);
}

// vectorized fp16 convert + 16-group permute: 4 contiguous LDG.128 in, 2 STG.128 out
__device__ __forceinline__ void conv16v(const float* __restrict__ src, __half* __restrict__ dst) {
    const float4 v0 = ((const float4*)src)[0];   // k0..3
    const float4 v1 = ((const float4*)src)[1];   // k4..7
    const float4 v2 = ((const float4*)src)[2];   // k8..11
    const float4 v3 = ((const float4*)src)[3];   // k12..15
    __half2 h[8];
    h[0] = __floats2half2_rn(v0.x, v0.y);
    h[1] = __floats2half2_rn(v2.x, v2.y);
    h[2] = __floats2half2_rn(v0.z, v0.w);
    h[3] = __floats2half2_rn(v2.z, v2.w);
    h[4] = __floats2half2_rn(v1.x, v1.y);
    h[5] = __floats2half2_rn(v3.x, v3.y);
    h[6] = __floats2half2_rn(v1.z, v1.w);
    h[7] = __floats2half2_rn(v3.z, v3.w);
    ((uint4*)dst)[0] = *(uint4*)&h[0];
    ((uint4*)dst)[1] = *(uint4*)&h[4];
}

// m16n8k16 fp16 HMMA, fp32 accum
__device__ __forceinline__ void mma16(float* d, uint2 lo, uint2 hi, uint2 b) {
    asm volatile(
        "mma.sync.aligned.m16n8k16.row.col.f32.f16.f16.f32 "
        "{%0,%1,%2,%3},{%4,%5,%6,%7},{%8,%9},{%0,%1,%2,%3};"
        : "+f"(d[0]), "+f"(d[1]), "+f"(d[2]), "+f"(d[3])
        : "r"(lo.x), "r"(hi.x), "r"(lo.y), "r"(hi.y), "r"(b.x), "r"(b.y));
}

// ---------------- smem layout: 4-stage multibuffer, 128m x 32c tile ----------------
// Stage = 64 k (128B of halves per row), row stride 144B. A:128 rows, B:192 rows.
#define ROWB 144
#define ROWH 72
#define STAGE_A_B (128 * ROWB)              // 18432
#define STAGE_B_B (192 * ROWB)              // 27648
#define SB_OFF_B  (4 * STAGE_A_B)           // 73728
#define BIAS_OFF_B (SB_OFF_B + 4 * STAGE_B_B)   // 184320
#define SMEM_TOT  (BIAS_OFF_B + 192 * 4)        // 185088

template <int K>
__device__ __forceinline__ void stage_load(uint32_t sbu,
                                           const __half* __restrict__ A,
                                           const __half* __restrict__ W,
                                           int m0, int c0, int s, int tid) {
    const int k0 = s * 64;
    const int b  = s & 3;
    // A: 128 rows x 8 chunks(16B); 2 threads/row, 4 chunks each
    const int ar = tid >> 1, ac0 = (tid & 1) * 4;
    const __half* asrc = A + (size_t)(m0 + ar) * K + k0;
    const uint32_t ad = sbu + b * STAGE_A_B + ar * ROWB;
    #pragma unroll
    for (int i = 0; i < 4; i++) cp16(ad + (ac0 + i) * 16, asrc + (ac0 + i) * 8);
    // B: 192 rows x 8 chunks; 6 chunks per thread
    const uint32_t wd = sbu + SB_OFF_B + b * STAGE_B_B;
    #pragma unroll
    for (int i = 0; i < 6; i++) {
        const int u = tid + 256 * i;
        const int r = u >> 3, ch = u & 7;
        const __half* wsrc = W + (size_t)((r >> 5) * 512 + c0 + (r & 31)) * K + k0 + ch * 8;
        cp16(wd + r * ROWB + ch * 16, wsrc);
    }
    asm volatile("cp.async.commit_group;" ::: "memory");
}

// ---------------- fused LSTM layer (mma.sync fp16, fp32 accum) ----------------
// CTA: 128 m-rows x 32 h-cols, 6 gate blocks (N_eff = 192). 8 warps = 4(m) x 2(n).
// PREPW1: blocks with blockIdx.y == 16 convert W1 -> g_w1 under the L0 GEMM.
template <int K, int LAYER, bool PREPW1>
__global__ void __launch_bounds__(256, 1)
lstm_mma(const float* __restrict__ bi, const float* __restrict__ bh,
         const float* __restrict__ W1src, float* __restrict__ out)
{
    constexpr int S = K / 64;       // 8 (L0) or 16 (L1)

    if (PREPW1 && blockIdx.y == 16) {
        // W1: 3072 rows x 64 groups = 196608 units; 64 blocks x 256 thr -> 12 each
        int gid = blockIdx.x * 256 + threadIdx.x;
        #pragma unroll 1
        for (int it = 0; it < 12; it++, gid += 16384) {
            const int row = gid >> 6, grp = gid & 63;
            conv16v(W1src + (size_t)(gbase(row >> 9) + (row & 511)) * 1024 + grp * 16,
                    g_w1 + (size_t)row * 1024 + grp * 16);
        }
        return;
    }

    extern __shared__ char smraw[];
    __half* sA = (__half*)smraw;
    __half* sB = (__half*)(smraw + SB_OFF_B);
    float* sbias = (float*)(smraw + BIAS_OFF_B);

    const __half* A = LAYER ? g_inp1 : g_a0;
    const __half* W = LAYER ? g_w1   : g_w0;

    const int tid = threadIdx.x, lane = tid & 31, w = tid >> 5;
    const int wm = w & 3, wn = w >> 2;
    const int m0 = blockIdx.x * 128, c0 = blockIdx.y * 32;

    const uint32_t sbu = s2u(smraw);

    stage_load<K>(sbu, A, W, m0, c0, 0, tid);

    if (tid < 192) {
        const int gr = gbase(tid >> 5) + c0 + (tid & 31);
        sbias[tid] = bi[gr] + bh[gr];
    }

    stage_load<K>(sbu, A, W, m0, c0, 1, tid);
    stage_load<K>(sbu, A, W, m0, c0, 2, tid);

    float acc0[12][4] = {}, acc1[12][4] = {};   // [gate*2+q][c] for m-tiles 0/1

    const __half* aB = sA + (wm * 32 + (lane >> 2)) * ROWH + 4 * (lane & 3);
    const __half* bB = sB + (wn * 16 + (lane >> 2)) * ROWH + 4 * (lane & 3);

    #pragma unroll 1
    for (int s = 0; s < S; s++) {
        // guarantee stage s complete: allow min(2, S-1-s) newer groups pending
        if (s < S - 2)      asm volatile("cp.async.wait_group 2;" ::: "memory");
        else if (s == S - 2) asm volatile("cp.async.wait_group 1;" ::: "memory");
        else                 asm volatile("cp.async.wait_group 0;" ::: "memory");
        __syncthreads();
        if (s + 3 < S) stage_load<K>(sbu, A, W, m0, c0, s + 3, tid);

        const int buf = s & 3;
        const __half* ab = aB + buf * (STAGE_A_B / 2);
        const __half* bb = bB + buf * (STAGE_B_B / 2);
        #pragma unroll
        for (int kg = 0; kg < 4; kg++) {
            const __half* abk = ab + kg * 16;
            const __half* bbk = bb + kg * 16;
            const uint2 A00 = *(const uint2*)(abk);
            const uint2 A01 = *(const uint2*)(abk + 8 * ROWH);
            const uint2 A10 = *(const uint2*)(abk + 16 * ROWH);
            const uint2 A11 = *(const uint2*)(abk + 24 * ROWH);
            uint2 bf[12];
            #pragma unroll
            for (int j = 0; j < 12; j++)
                bf[j] = *(const uint2*)(bbk + ((j >> 1) * 32 + (j & 1) * 8) * ROWH);
            #pragma unroll
            for (int j = 0; j < 12; j++) {
                mma16(acc0[j], A00, A01, bf[j]);
                mma16(acc1[j], A10, A11, bf[j]);
            }
        }
    }

    // -------- epilogue: activations fused in registers --------
    #pragma unroll
    for (int im = 0; im < 2; im++) {
        float (*acc)[4] = im ? acc1 : acc0;
        #pragma unroll
        for (int rh = 0; rh < 2; rh++) {
            const int m = m0 + wm * 32 + im * 16 + rh * 8 + (lane >> 2);
            const int bb2 = m >> 8;
            const bool lastt = (m & 255) == 255;
            #pragma unroll
            for (int q = 0; q < 2; q++) {
                const int hcl = wn * 16 + q * 8 + 2 * (lane & 3);
                float hf[2], hbk[2], cfv[2], hs[2];
                #pragma unroll
                for (int j2 = 0; j2 < 2; j2++) {
                    const int c  = rh * 2 + j2;
                    const int hc = hcl + j2;
                    const float zi = acc[0 + q][c]  + sbias[hc];
                    const float zg = acc[2 + q][c]  + sbias[32 + hc];
                    const float zo = acc[4 + q][c]  + sbias[64 + hc];
                    const float cc = sigm(zi) * tanh_ap(zg);
                    const float h0 = sigm(zo) * tanh_ap(cc);
                    const float yi = acc[6 + q][c]  + sbias[96 + hc];
                    const float yg = acc[8 + q][c]  + sbias[128 + hc];
                    const float yo = acc[10 + q][c] + sbias[160 + hc];
                    const float cb = sigm(yi) * tanh_ap(yg);
                    const float h1 = sigm(yo) * tanh_ap(cb);
                    hf[j2] = h0; hbk[j2] = h1; cfv[j2] = cc; hs[j2] = h0 + h1;
                }
                const int hcg = c0 + hcl;
                *(float2*)(out + OUT_ENC_OFF + ((size_t)m * 2 + LAYER) * 512 + hcg) =
                    make_float2(hs[0], hs[1]);
                if (LAYER == 0) {
                    __half* ip = g_inp1 + (size_t)m * 1024;
                    *(__half2*)(ip + kslot16(hcg))       = __floats2half2_rn(hf[0], hf[1]);
                    *(__half2*)(ip + kslot16(512 + hcg)) = __floats2half2_rn(hbk[0], hbk[1]);
                }
                if (lastt) {
                    *(float2*)(out + (LAYER * 32 + bb2) * 512 + hcg) =
                        make_float2(hf[0], hf[1]);
                    *(float2*)(out + OUT_C_OFF + (LAYER * 32 + bb2) * 512 + hcg) =
                        make_float2(cfv[0], cfv[1]);
                }
            }
        }
    }
}

// ---------------- prep kernel: embeddings + W0, 2 units/thread for MLP ----------------
// ranges: [0,262144) emb (8192 rows x 32 grp) | [262144,360448) w0 (3072 x 32)
__global__ void prep_aw0(const int* __restrict__ x, const float* __restrict__ emb,
                         const float* __restrict__ W0) {
    int id = blockIdx.x * 256 + threadIdx.x;
    #pragma unroll
    for (int rep = 0; rep < 2; rep++, id += 180224) {
        if (id < 262144) {
            const int m = id >> 5, grp = id & 31;
            conv16v(emb + (size_t)x[m] * 512 + grp * 16, g_a0 + (size_t)m * 512 + grp * 16);
        } else {
            const int u = id - 262144;
            const int row = u >> 5, grp = u & 31;
            conv16v(W0 + (size_t)(gbase(row >> 9) + (row & 511)) * 512 + grp * 16,
                    g_w0 + (size_t)row * 512 + grp * 16);
        }
    }
}

// ---------------- launch ----------------
extern "C" void kernel_launch(void* const* d_in, const int* in_sizes, int n_in,
                              void* d_out, int out_size)
{
    const int*   x   = (const int*)  d_in[0];
    const float* emb = (const float*)d_in[1];
    const float* W0  = (const float*)d_in[2];
    const float* bi0 = (const float*)d_in[4];
    const float* bh0 = (const float*)d_in[5];
    const float* W1  = (const float*)d_in[6];
    const float* bi1 = (const float*)d_in[8];
    const float* bh1 = (const float*)d_in[9];
    float* out = (float*)d_out;

    cudaFuncSetAttribute(lstm_mma<512, 0, true>,
                         cudaFuncAttributeMaxDynamicSharedMemorySize, SMEM_TOT);
    cudaFuncSetAttribute(lstm_mma<1024, 1, false>,
                         cudaFuncAttributeMaxDynamicSharedMemorySize, SMEM_TOT);

    prep_aw0<<<704, 256>>>(x, emb, W0);   // 704*256*2 = 360448 units

    dim3 g0(64, 17);   // y==16 blocks convert W1 under cover of the L0 GEMM
    lstm_mma<512, 0, true><<<g0, 256, SMEM_TOT>>>(bi0, bh0, W1, out);
    dim3 g1(64, 16);
    lstm_mma<1024, 1, false><<<g1, 256, SMEM_TOT>>>(bi1, bh1, nullptr, out);
}

// round 13
// speedup vs baseline: 1.5759x; 1.5759x over previous
#include <cuda_runtime.h>
#include <cuda_fp16.h>
#include <cstdint>

// ---------------- problem constants ----------------
#define OUT_C_OFF   (2 * 32 * 512)
#define OUT_ENC_OFF (4 * 32 * 512)
#define NTILES      1024            // 64 m-tiles x 16 c-tiles per layer
#define NCTAS       148

// ---------------- device scratch (no allocs allowed) ----------------
// GEMM operands rn-rounded to fp16, k-permuted within each 16-group to
// [0,1,8,9, 2,3,10,11, 4,5,12,13, 6,7,14,15] so each thread's m16n8k16
// fragment (k = 2q,2q+1,2q+8,2q+9) is one contiguous LDS.64.
__device__ __half g_a0[(size_t)8192 * 512];     // gathered embeddings
__device__ __half g_w0[(size_t)3072 * 512];     // L0 weights, gate-major: i_f,g_f,o_f,i_b,g_b,o_b
__device__ __half g_w1[(size_t)3072 * 1024];    // L1 weights, gate-major
__device__ __half g_inp1[(size_t)8192 * 1024];  // L0 output h (permuted): [h_f | h_b]

// ---------------- helpers ----------------
__device__ __forceinline__ float tanh_ap(float x) {
    float r; asm("tanh.approx.f32 %0, %1;" : "=f"(r) : "f"(x)); return r;
}
__device__ __forceinline__ float sigm(float x) { return 0.5f * tanh_ap(0.5f * x) + 0.5f; }

__device__ __forceinline__ uint32_t s2u(const void* p) {
    uint32_t a;
    asm("{ .reg .u64 t; cvta.to.shared.u64 t, %1; cvt.u32.u64 %0, t; }" : "=r"(a) : "l"(p));
    return a;
}
__device__ __forceinline__ void cp16(uint32_t d, const void* s) {
    asm volatile("cp.async.cg.shared.global [%0], [%1], 16;" :: "r"(d), "l"(s));
}

// logical k L -> stored slot (within 16-group)
__device__ __forceinline__ int kslot16(int L) {
    const int r = L & 15, base = L & ~15;
    return base + ((r < 8) ? (((r >> 1) << 2) + (r & 1))
                           : ((((r - 8) >> 1) << 2) + 2 + (r & 1)));
}

// gate g (0..5 = i_f,g_f,o_f,i_b,g_b,o_b) -> row base in (2,4H) space
__device__ __forceinline__ int gbase(int g) {
    const int d = (g >= 3) ? 1 : 0;
    const int g3 = g - 3 * d;
    return d * 2048 + ((g3 == 1) ? 1024 : (g3 == 2) ? 1536 : 0);
}

// vectorized fp16 convert + 16-group permute: 4 contiguous LDG.128 in, 2 STG.128 out
__device__ __forceinline__ void conv16v(const float* __restrict__ src, __half* __restrict__ dst) {
    const float4 v0 = ((const float4*)src)[0];   // k0..3
    const float4 v1 = ((const float4*)src)[1];   // k4..7
    const float4 v2 = ((const float4*)src)[2];   // k8..11
    const float4 v3 = ((const float4*)src)[3];   // k12..15
    __half2 h[8];
    h[0] = __floats2half2_rn(v0.x, v0.y);
    h[1] = __floats2half2_rn(v2.x, v2.y);
    h[2] = __floats2half2_rn(v0.z, v0.w);
    h[3] = __floats2half2_rn(v2.z, v2.w);
    h[4] = __floats2half2_rn(v1.x, v1.y);
    h[5] = __floats2half2_rn(v3.x, v3.y);
    h[6] = __floats2half2_rn(v1.z, v1.w);
    h[7] = __floats2half2_rn(v3.z, v3.w);
    ((uint4*)dst)[0] = *(uint4*)&h[0];
    ((uint4*)dst)[1] = *(uint4*)&h[4];
}

// m16n8k16 fp16 HMMA, fp32 accum
__device__ __forceinline__ void mma16(float* d, uint2 lo, uint2 hi, uint2 b) {
    asm volatile(
        "mma.sync.aligned.m16n8k16.row.col.f32.f16.f16.f32 "
        "{%0,%1,%2,%3},{%4,%5,%6,%7},{%8,%9},{%0,%1,%2,%3};"
        : "+f"(d[0]), "+f"(d[1]), "+f"(d[2]), "+f"(d[3])
        : "r"(lo.x), "r"(hi.x), "r"(lo.y), "r"(hi.y), "r"(b.x), "r"(b.y));
}

// ---------------- smem layout: 3-stage multibuffer, 128m x 32c tile (R10) ----------------
#define ROWB 144
#define ROWH 72
#define STAGE_A_B (128 * ROWB)              // 18432
#define STAGE_B_B (192 * ROWB)              // 27648
#define SB_OFF_B  (3 * STAGE_A_B)           // 55296
#define BIAS_OFF_B (SB_OFF_B + 3 * STAGE_B_B)   // 138240
#define SMEM_TOT  (BIAS_OFF_B + 192 * 4)        // 139008

template <int K>
__device__ __forceinline__ void stage_load(uint32_t sbu,
                                           const __half* __restrict__ A,
                                           const __half* __restrict__ W,
                                           int m0, int c0, int k0, int buf, int tid) {
    // A: 128 rows x 8 chunks(16B); 2 threads/row, 4 chunks each
    const int ar = tid >> 1, ac0 = (tid & 1) * 4;
    const __half* asrc = A + (size_t)(m0 + ar) * K + k0;
    const uint32_t ad = sbu + buf * STAGE_A_B + ar * ROWB;
    #pragma unroll
    for (int i = 0; i < 4; i++) cp16(ad + (ac0 + i) * 16, asrc + (ac0 + i) * 8);
    // B: 192 rows x 8 chunks; 6 chunks per thread
    const uint32_t wd = sbu + SB_OFF_B + buf * STAGE_B_B;
    #pragma unroll
    for (int i = 0; i < 6; i++) {
        const int u = tid + 256 * i;
        const int r = u >> 3, ch = u & 7;
        const __half* wsrc = W + (size_t)((r >> 5) * 512 + c0 + (r & 31)) * K + k0 + ch * 8;
        cp16(wd + r * ROWB + ch * 16, wsrc);
    }
    asm volatile("cp.async.commit_group;" ::: "memory");
}

// ---------------- persistent fused LSTM layer (mma.sync fp16, fp32 accum) ----------------
// 148 CTAs; CTA walks tiles t = bid, bid+148, ... (tile = 128m x 32c x 6 gates).
// Load cursor runs 2 stages ahead of compute ACROSS tile boundaries; empty
// cp.async groups keep wait_group 1 semantics uniform at the tail.
template <int K, int LAYER, bool PREPW1>
__global__ void __launch_bounds__(256, 1)
lstm_mma(const float* __restrict__ bi, const float* __restrict__ bh,
         const float* __restrict__ W1src, float* __restrict__ out)
{
    constexpr int S = K / 64;       // 8 (L0) or 16 (L1)

    extern __shared__ char smraw[];
    __half* sA = (__half*)smraw;
    __half* sB = (__half*)(smraw + SB_OFF_B);
    float* sbias = (float*)(smraw + BIAS_OFF_B);

    const __half* A = LAYER ? g_inp1 : g_a0;
    const __half* W = LAYER ? g_w1   : g_w0;

    const int tid = threadIdx.x, lane = tid & 31, w = tid >> 5;
    const int wm = w & 3, wn = w >> 2;
    const uint32_t sbu = s2u(smraw);

    // ---- load cursor (tile lt, stage ls), compute counter g ----
    int lt = blockIdx.x, ls = 0;
    int lbuf = 0;                    // issued % 3
    #pragma unroll
    for (int i = 0; i < 2; i++) {    // prologue: 2 stages ahead
        stage_load<K>(sbu, A, W, (lt >> 4) * 128, (lt & 15) * 32, ls * 64, lbuf, tid);
        if (++lbuf == 3) lbuf = 0;
        if (++ls == S) { ls = 0; lt += NCTAS; }
    }
    int cbuf = 0;                    // g % 3

    const __half* aB = sA + (wm * 32 + (lane >> 2)) * ROWH + 4 * (lane & 3);
    const __half* bB = sB + (wn * 16 + (lane >> 2)) * ROWH + 4 * (lane & 3);

    #pragma unroll 1
    for (int t = blockIdx.x; t < NTILES; t += NCTAS) {
        const int m0 = (t >> 4) * 128, c0 = (t & 15) * 32;
        float acc0[12][4] = {}, acc1[12][4] = {};

        #pragma unroll 1
        for (int s = 0; s < S; s++) {
            asm volatile("cp.async.wait_group 1;" ::: "memory");
            __syncthreads();
            if (s == 0 && tid < 192) {   // this tile's bias (read only at epilogue)
                const int gr = gbase(tid >> 5) + c0 + (tid & 31);
                sbias[tid] = bi[gr] + bh[gr];
            }
            if (lt < NTILES) {
                stage_load<K>(sbu, A, W, (lt >> 4) * 128, (lt & 15) * 32, ls * 64, lbuf, tid);
                if (++ls == S) { ls = 0; lt += NCTAS; }
            } else {
                asm volatile("cp.async.commit_group;" ::: "memory");  // empty group
            }
            if (++lbuf == 3) lbuf = 0;

            const __half* ab = aB + cbuf * (STAGE_A_B / 2);
            const __half* bb = bB + cbuf * (STAGE_B_B / 2);
            if (++cbuf == 3) cbuf = 0;
            #pragma unroll
            for (int kg = 0; kg < 4; kg++) {
                const __half* abk = ab + kg * 16;
                const __half* bbk = bb + kg * 16;
                const uint2 A00 = *(const uint2*)(abk);
                const uint2 A01 = *(const uint2*)(abk + 8 * ROWH);
                const uint2 A10 = *(const uint2*)(abk + 16 * ROWH);
                const uint2 A11 = *(const uint2*)(abk + 24 * ROWH);
                uint2 bf[12];
                #pragma unroll
                for (int j = 0; j < 12; j++)
                    bf[j] = *(const uint2*)(bbk + ((j >> 1) * 32 + (j & 1) * 8) * ROWH);
                #pragma unroll
                for (int j = 0; j < 12; j++) {
                    mma16(acc0[j], A00, A01, bf[j]);
                    mma16(acc1[j], A10, A11, bf[j]);
                }
            }
        }

        // -------- epilogue: activations fused in registers --------
        #pragma unroll
        for (int im = 0; im < 2; im++) {
            float (*acc)[4] = im ? acc1 : acc0;
            #pragma unroll
            for (int rh = 0; rh < 2; rh++) {
                const int m = m0 + wm * 32 + im * 16 + rh * 8 + (lane >> 2);
                const int bb2 = m >> 8;
                const bool lastt = (m & 255) == 255;
                #pragma unroll
                for (int q = 0; q < 2; q++) {
                    const int hcl = wn * 16 + q * 8 + 2 * (lane & 3);
                    float hf[2], hbk[2], cfv[2], hs[2];
                    #pragma unroll
                    for (int j2 = 0; j2 < 2; j2++) {
                        const int c  = rh * 2 + j2;
                        const int hc = hcl + j2;
                        const float zi = acc[0 + q][c]  + sbias[hc];
                        const float zg = acc[2 + q][c]  + sbias[32 + hc];
                        const float zo = acc[4 + q][c]  + sbias[64 + hc];
                        const float cc = sigm(zi) * tanh_ap(zg);
                        const float h0 = sigm(zo) * tanh_ap(cc);
                        const float yi = acc[6 + q][c]  + sbias[96 + hc];
                        const float yg = acc[8 + q][c]  + sbias[128 + hc];
                        const float yo = acc[10 + q][c] + sbias[160 + hc];
                        const float cb = sigm(yi) * tanh_ap(yg);
                        const float h1 = sigm(yo) * tanh_ap(cb);
                        hf[j2] = h0; hbk[j2] = h1; cfv[j2] = cc; hs[j2] = h0 + h1;
                    }
                    const int hcg = c0 + hcl;
                    *(float2*)(out + OUT_ENC_OFF + ((size_t)m * 2 + LAYER) * 512 + hcg) =
                        make_float2(hs[0], hs[1]);
                    if (LAYER == 0) {
                        __half* ip = g_inp1 + (size_t)m * 1024;
                        *(__half2*)(ip + kslot16(hcg))       = __floats2half2_rn(hf[0], hf[1]);
                        *(__half2*)(ip + kslot16(512 + hcg)) = __floats2half2_rn(hbk[0], hbk[1]);
                    }
                    if (lastt) {
                        *(float2*)(out + (LAYER * 32 + bb2) * 512 + hcg) =
                            make_float2(hf[0], hf[1]);
                        *(float2*)(out + OUT_C_OFF + (LAYER * 32 + bb2) * 512 + hcg) =
                            make_float2(cfv[0], cfv[1]);
                    }
                }
            }
        }

        // -------- W1 conversion chunk (L0 only): 192 units per tile, exact cover --------
        if (PREPW1 && tid < 192) {
            const int u = t * 192 + tid;           // < 196608 always
            const int row = u >> 6, grp = u & 63;
            conv16v(W1src + (size_t)(gbase(row >> 9) + (row & 511)) * 1024 + grp * 16,
                    g_w1 + (size_t)row * 1024 + grp * 16);
        }
    }
}

// ---------------- prep kernel: embeddings + W0 (R10 version) ----------------
// ranges: [0,262144) emb (8192 rows x 32 grp) | [262144,360448) w0 (3072 x 32)
__global__ void prep_aw0(const int* __restrict__ x, const float* __restrict__ emb,
                         const float* __restrict__ W0) {
    const int id = blockIdx.x * 256 + threadIdx.x;
    if (id < 262144) {
        const int m = id >> 5, grp = id & 31;
        conv16v(emb + (size_t)x[m] * 512 + grp * 16, g_a0 + (size_t)m * 512 + grp * 16);
    } else {
        const int u = id - 262144;
        const int row = u >> 5, grp = u & 31;
        conv16v(W0 + (size_t)(gbase(row >> 9) + (row & 511)) * 512 + grp * 16,
                g_w0 + (size_t)row * 512 + grp * 16);
    }
}

// ---------------- launch ----------------
extern "C" void kernel_launch(void* const* d_in, const int* in_sizes, int n_in,
                              void* d_out, int out_size)
{
    const int*   x   = (const int*)  d_in[0];
    const float* emb = (const float*)d_in[1];
    const float* W0  = (const float*)d_in[2];
    const float* bi0 = (const float*)d_in[4];
    const float* bh0 = (const float*)d_in[5];
    const float* W1  = (const float*)d_in[6];
    const float* bi1 = (const float*)d_in[8];
    const float* bh1 = (const float*)d_in[9];
    float* out = (float*)d_out;

    cudaFuncSetAttribute(lstm_mma<512, 0, true>,
                         cudaFuncAttributeMaxDynamicSharedMemorySize, SMEM_TOT);
    cudaFuncSetAttribute(lstm_mma<1024, 1, false>,
                         cudaFuncAttributeMaxDynamicSharedMemorySize, SMEM_TOT);

    prep_aw0<<<1408, 256>>>(x, emb, W0);

    lstm_mma<512, 0, true><<<NCTAS, 256, SMEM_TOT>>>(bi0, bh0, W1, out);
    lstm_mma<1024, 1, false><<<NCTAS, 256, SMEM_TOT>>>(bi1, bh1, nullptr, out);
}